// round 6
// baseline (speedup 1.0000x reference)
#include <cuda_runtime.h>
#include <stdint.h>

// Problem constants
#define N_V   16384
#define N_E   8192
#define CIN   128
#define COUT  64
#define LOG_M 13

// Extraction config (R1-proven)
#define GEMMB    64                        // GEMM co-blocks at front of grid
#define EBLOCKS  2048
#define ETHREADS 256
#define CAPB     512                       // COO slots per block (mean ~328, 10 sigma safe)
#define NTOT     (EBLOCKS*ETHREADS)        // 524288 extract threads
#define EITER    64                        // (N_V*N_E/4)/NTOT exactly
#define TOT4     (N_V*(N_E/4))

// ---------------- scratch (device globals; no allocation) ----------------
__device__ int            g_deg_v[N_V];
__device__ int            g_deg_e[N_E];
__device__ int            g_cur_v[N_V];
__device__ int            g_cur_e[N_E];
__device__ int            g_off_v[N_V + 1];
__device__ int            g_off_e[N_E + 1];
__device__ int            g_blk_cnt[EBLOCKS];
__device__ unsigned int   g_coo[EBLOCKS * CAPB];     // packed (i<<13)|j
__device__ unsigned short g_adj_v[EBLOCKS * CAPB];   // CSR by vertex: edge ids
__device__ unsigned short g_adj_e[EBLOCKS * CAPB];   // CSC by edge: vertex ids
__device__ float          g_dv[N_V];
__device__ float          g_de[N_E];
__device__ float          g_Z[N_V * COUT];           // X W^T + b (dv folded in k_edge)
__device__ float          g_Y2[N_E * COUT];          // de * (H^T @ dv.Z)

// ---------------- kernel 1: extract (blocks 64..2111) || GEMM (blocks 0..63) ----
__global__ void k_ext_gemm(const float* __restrict__ H,
                           const float* __restrict__ X,
                           const float* __restrict__ W,
                           const float* __restrict__ bias) {
    __shared__ __align__(16) unsigned char sb[4096];
    const int tid  = threadIdx.x;
    const int bx   = blockIdx.x;
    const int wid  = tid >> 5;
    const int lane = tid & 31;

    if (bx < GEMMB) {
        // Z[i][c] = sum_k X[i][k]*W[c][k] + b[c]; warp per row (R4-proven).
        // X row staged in per-warp smem (512B); W rows streamed per-lane (L1-hot).
        float4* srow4 = (float4*)(sb + wid * 512);     // 32 float4 per warp
        const float4* __restrict__ X4 = (const float4*)X;
        const float4* __restrict__ Wc0 = (const float4*)(W + lane * CIN);
        const float4* __restrict__ Wc1 = (const float4*)(W + (lane + 32) * CIN);
        float b0 = bias[lane], b1 = bias[lane + 32];
        int gw = bx * 8 + wid;                         // 0..511
        for (int r = 0; r < 32; r++) {                 // 512 warps x 32 rows = 16384
            int i = gw * 32 + r;
            srow4[lane] = X4[i * 32 + lane];           // full 128-float row
            __syncwarp();
            float a0 = 0.f, a1 = 0.f;
#pragma unroll
            for (int k4 = 0; k4 < 32; k4++) {
                float4 xv = srow4[k4];
                float4 w0 = Wc0[k4];
                float4 w1 = Wc1[k4];
                a0 += xv.x * w0.x + xv.y * w0.y + xv.z * w0.z + xv.w * w0.w;
                a1 += xv.x * w1.x + xv.y * w1.y + xv.z * w1.z + xv.w * w1.w;
            }
            g_Z[i * COUT + lane]      = a0 + b0;
            g_Z[i * COUT + lane + 32] = a1 + b1;
            __syncwarp();                              // srow reuse next row
        }
        return;
    }

    // ---- streaming extract over H (536 MB), R1-identical config ----
    int* s_cnt = (int*)sb;
    if (tid == 0) *s_cnt = 0;
    __syncthreads();

    const uint4* __restrict__ H4 = (const uint4*)H;
    int eb = bx - GEMMB;
    int etid = eb * ETHREADS + tid;
    unsigned cooBase = (unsigned)eb * CAPB;

#pragma unroll 4
    for (int it = 0; it < EITER; it++) {
        int v = etid + it * NTOT;                      // < TOT4
        uint4 h = __ldcs(&H4[v]);
        if ((h.x | h.y | h.z | h.w) == 0u) continue;   // ~98% of vectors
        int e = v * 4;
#pragma unroll
        for (int c = 0; c < 4; c++) {
            unsigned hv = (c == 0) ? h.x : (c == 1) ? h.y : (c == 2) ? h.z : h.w;
            if (hv) {
                int ee = e + c;
                int i = ee >> LOG_M;
                int j = ee & (N_E - 1);
                atomicAdd(&g_deg_v[i], 1);
                atomicAdd(&g_deg_e[j], 1);
                int p = atomicAdd(s_cnt, 1);           // shared atomic: cheap
                if (p < CAPB)
                    g_coo[cooBase + p] = ((unsigned)i << LOG_M) | (unsigned)j;
            }
        }
    }
    __syncthreads();
    if (tid == 0)
        g_blk_cnt[eb] = (*s_cnt < CAPB) ? *s_cnt : CAPB;
}

// ---------------- kernel 2: prefix scan + scales (2 blocks x 256) ----------------
__device__ void scan_scale(int n, int per, const int* __restrict__ deg,
                           int* __restrict__ off, float* __restrict__ sc, bool isV) {
    __shared__ int part[256];
    int tid = threadIdx.x;
    int base = tid * per;
    int s = 0;
    for (int k = 0; k < per; k++) s += deg[base + k];
    part[tid] = s;
    __syncthreads();
    for (int d = 1; d < 256; d <<= 1) {
        int v = (tid >= d) ? part[tid - d] : 0;
        __syncthreads();
        part[tid] += v;
        __syncthreads();
    }
    int pre = tid ? part[tid - 1] : 0;
    for (int k = 0; k < per; k++) {
        int d = deg[base + k];
        off[base + k] = pre;
        pre += d;
        sc[base + k] = (d > 0) ? (isV ? rsqrtf((float)d) : 1.0f / (float)d) : 0.0f;
    }
    if (tid == 255) off[n] = pre;
}

__global__ void k_scan_scales() {
    if (blockIdx.x == 0) scan_scale(N_V, 64, g_deg_v, g_off_v, g_dv, true);
    else                 scan_scale(N_E, 32, g_deg_e, g_off_e, g_de, false);
}

// ---------------- kernel 3: bucket COO into CSR(vertex) + CSC(edge) ----------------
__global__ void k_bucket() {
    int idx = blockIdx.x * blockDim.x + threadIdx.x;   // over EBLOCKS*CAPB slots
    int blk = idx >> 9;                                // CAPB = 512
    int loc = idx & (CAPB - 1);
    if (loc >= g_blk_cnt[blk]) return;
    unsigned p = g_coo[idx];
    int i = p >> LOG_M;
    int j = p & (N_E - 1);
    int pv = atomicAdd(&g_cur_v[i], 1);
    g_adj_v[g_off_v[i] + pv] = (unsigned short)j;
    int pe = atomicAdd(&g_cur_e[j], 1);
    g_adj_e[g_off_e[j] + pe] = (unsigned short)i;
}

// ---------------- kernel 4: Y2[j] = de_j * sum_{i in j} dv_i * Z[i] ----------------
__global__ void k_edge() {
    int w = (blockIdx.x * blockDim.x + threadIdx.x) >> 5;
    int lane = threadIdx.x & 31;
    if (w >= N_E) return;
    int t = g_off_e[w], end = g_off_e[w + 1];
    float a0 = 0.f, a1 = 0.f, b0 = 0.f, b1 = 0.f;
    for (; t + 2 <= end; t += 2) {
        int i0 = g_adj_e[t], i1 = g_adj_e[t + 1];
        float s0 = g_dv[i0], s1 = g_dv[i1];
        const float* z0 = g_Z + i0 * COUT;
        const float* z1 = g_Z + i1 * COUT;
        a0 += s0 * z0[lane]; a1 += s0 * z0[lane + 32];
        b0 += s1 * z1[lane]; b1 += s1 * z1[lane + 32];
    }
    if (t < end) {
        int i0 = g_adj_e[t];
        float s0 = g_dv[i0];
        const float* z0 = g_Z + i0 * COUT;
        a0 += s0 * z0[lane]; a1 += s0 * z0[lane + 32];
    }
    float de = g_de[w];
    g_Y2[w * COUT + lane]      = (a0 + b0) * de;
    g_Y2[w * COUT + lane + 32] = (a1 + b1) * de;
}

// ---------------- kernel 5: out = relu(dv .* (H @ Y2)) + counter reset ----------------
__global__ void k_vertex(float* __restrict__ out) {
    int gt = blockIdx.x * blockDim.x + threadIdx.x;
    int w = gt >> 5;
    int lane = threadIdx.x & 31;
    if (w < N_V) {
        int t = g_off_v[w], end = g_off_v[w + 1];
        float a0 = 0.f, a1 = 0.f, b0 = 0.f, b1 = 0.f;
        for (; t + 2 <= end; t += 2) {
            int j0 = g_adj_v[t], j1 = g_adj_v[t + 1];
            const float* y0 = g_Y2 + j0 * COUT;
            const float* y1 = g_Y2 + j1 * COUT;
            a0 += y0[lane]; a1 += y0[lane + 32];
            b0 += y1[lane]; b1 += y1[lane + 32];
        }
        if (t < end) {
            int j0 = g_adj_v[t];
            const float* y0 = g_Y2 + j0 * COUT;
            a0 += y0[lane]; a1 += y0[lane + 32];
        }
        float dv = g_dv[w];
        float o0 = dv * (a0 + b0);
        float o1 = dv * (a1 + b1);
        out[w * COUT + lane]      = o0 > 0.f ? o0 : 0.f;
        out[w * COUT + lane + 32] = o1 > 0.f ? o1 : 0.f;
    }
    // tail: re-zero counters for the NEXT launch (launch 0 covered by static
    // zero-init of __device__ globals; launches are stream-ordered).
    if (gt < N_V) { g_deg_v[gt] = 0; g_cur_v[gt] = 0; }
    if (gt < N_E) { g_deg_e[gt] = 0; g_cur_e[gt] = 0; }
}

// ---------------- launch ----------------
extern "C" void kernel_launch(void* const* d_in, const int* in_sizes, int n_in,
                              void* d_out, int out_size) {
    const float* X = (const float*)d_in[0];   // (16384, 128)
    const float* H = (const float*)d_in[1];   // (16384, 8192)
    const float* W = (const float*)d_in[2];   // (64, 128)
    const float* b = (const float*)d_in[3];   // (64,)
    float* out = (float*)d_out;               // (16384, 64)

    k_ext_gemm   <<<GEMMB + EBLOCKS, ETHREADS>>>(H, X, W, b);
    k_scan_scales<<<2, 256>>>();
    k_bucket     <<<(EBLOCKS * CAPB) / 256, 256>>>();
    k_edge       <<<(N_E * 32) / 256, 256>>>();
    k_vertex     <<<(N_V * 32) / 256, 256>>>(out);
}

// round 7
// speedup vs baseline: 2.8336x; 2.8336x over previous
#include <cuda_runtime.h>
#include <stdint.h>

// Problem constants
#define N_V   16384
#define N_E   8192
#define CIN   128
#define COUT  64
#define LOG_M 13

// Extraction config (R1-proven, DO NOT TOUCH)
#define EBLOCKS  2048
#define ETHREADS 256
#define CAPB     512                       // COO slots per block (mean ~328, 10 sigma safe)
#define NTOT     (EBLOCKS*ETHREADS)        // 524288 threads
#define EITER    64                        // (N_V*N_E/4)/NTOT exactly

// ---------------- scratch (device globals; no allocation) ----------------
__device__ int            g_deg_v[N_V];
__device__ int            g_deg_e[N_E];
__device__ int            g_cur_v[N_V];
__device__ int            g_cur_e[N_E];
__device__ int            g_off_v[N_V + 1];
__device__ int            g_off_e[N_E + 1];
__device__ int            g_blk_cnt[EBLOCKS];
__device__ unsigned int   g_coo[EBLOCKS * CAPB];     // packed (i<<13)|j
__device__ unsigned short g_adj_v[EBLOCKS * CAPB];   // CSR by vertex: edge ids
__device__ unsigned short g_adj_e[EBLOCKS * CAPB];   // CSC by edge: vertex ids
__device__ float          g_dv[N_V];
__device__ float          g_de[N_E];
__device__ float          g_Z[N_V * COUT];           // dv * (X W^T + b)
__device__ float          g_Y2[N_E * COUT];          // de * (H^T @ Z)

// ---------------- kernel 1: extract (EXACT R1 shape) ----------------
__global__ void k_extract(const float* __restrict__ H) {
    __shared__ int s_cnt;
    if (threadIdx.x == 0) s_cnt = 0;
    __syncthreads();

    const uint4* __restrict__ H4 = (const uint4*)H;
    int tid = blockIdx.x * ETHREADS + threadIdx.x;
    unsigned cooBase = blockIdx.x * CAPB;

#pragma unroll 4
    for (int it = 0; it < EITER; it++) {
        int v = tid + it * NTOT;
        uint4 h = H4[v];
        if ((h.x | h.y | h.z | h.w) == 0u) continue;   // ~98% of vectors
        int e = v * 4;
#pragma unroll
        for (int c = 0; c < 4; c++) {
            unsigned hv = (c == 0) ? h.x : (c == 1) ? h.y : (c == 2) ? h.z : h.w;
            if (hv) {
                int ee = e + c;
                int i = ee >> LOG_M;
                int j = ee & (N_E - 1);
                atomicAdd(&g_deg_v[i], 1);
                atomicAdd(&g_deg_e[j], 1);
                int p = atomicAdd(&s_cnt, 1);          // shared atomic: cheap
                if (p < CAPB)
                    g_coo[cooBase + p] = ((unsigned)i << LOG_M) | (unsigned)j;
            }
        }
    }
    __syncthreads();
    if (threadIdx.x == 0)
        g_blk_cnt[blockIdx.x] = (s_cnt < CAPB) ? s_cnt : CAPB;
}

// ---------------- kernel 2: prefix scan + scales fused (2 blocks x 256) --------
__device__ void scan_scale(int n, int per, const int* __restrict__ deg,
                           int* __restrict__ off, float* __restrict__ sc, bool isV) {
    __shared__ int part[256];
    int tid = threadIdx.x;
    int base = tid * per;
    int s = 0;
    for (int k = 0; k < per; k++) s += deg[base + k];
    part[tid] = s;
    __syncthreads();
    for (int d = 1; d < 256; d <<= 1) {
        int v = (tid >= d) ? part[tid - d] : 0;
        __syncthreads();
        part[tid] += v;
        __syncthreads();
    }
    int pre = tid ? part[tid - 1] : 0;
    for (int k = 0; k < per; k++) {
        int d = deg[base + k];
        off[base + k] = pre;
        pre += d;
        sc[base + k] = (d > 0) ? (isV ? rsqrtf((float)d) : 1.0f / (float)d) : 0.0f;
    }
    if (tid == 255) off[n] = pre;
}

__global__ void k_scan_scales() {
    if (blockIdx.x == 0) scan_scale(N_V, 64, g_deg_v, g_off_v, g_dv, true);
    else                 scan_scale(N_E, 32, g_deg_e, g_off_e, g_de, false);
}

// ---------------- kernel 3: bucket COO into CSR(vertex) + CSC(edge) ------------
__global__ void k_bucket() {
    int idx = blockIdx.x * blockDim.x + threadIdx.x;   // over EBLOCKS*CAPB slots
    int blk = idx >> 9;                                // CAPB = 512
    int loc = idx & (CAPB - 1);
    if (loc >= g_blk_cnt[blk]) return;
    unsigned p = g_coo[idx];
    int i = p >> LOG_M;
    int j = p & (N_E - 1);
    int pv = atomicAdd(&g_cur_v[i], 1);
    g_adj_v[g_off_v[i] + pv] = (unsigned short)j;
    int pe = atomicAdd(&g_cur_e[j], 1);
    g_adj_e[g_off_e[j] + pe] = (unsigned short)i;
}

// ---------------- kernel 4: GEMM  Z = dv .* (X W^T + b)  (EXACT R1 shape) -------
__global__ void k_gemm(const float* __restrict__ X,
                       const float* __restrict__ W,
                       const float* __restrict__ b) {
    __shared__ float Xs[32 * 128];   // 16 KB
    __shared__ float Ws[128 * 64];   // 32 KB  [k][c]
    int tid = threadIdx.x;           // 128 threads
    int row0 = blockIdx.x * 32;

    const float4* __restrict__ Xg = (const float4*)(X + row0 * CIN);
    float4* Xs4 = (float4*)Xs;
#pragma unroll
    for (int t = 0; t < 8; t++) Xs4[tid + t * 128] = Xg[tid + t * 128];

#pragma unroll
    for (int t = 0; t < 64; t++) {
        int idx = tid + t * 128;     // idx = k*64 + c
        int k = idx >> 6, c = idx & 63;
        Ws[idx] = W[c * CIN + k];
    }
    __syncthreads();

    int cx = (tid & 15) * 4;
    int ry = (tid >> 4) * 4;
    float acc[4][4] = {};

#pragma unroll
    for (int k = 0; k < 128; k += 4) {
        float4 wv[4], xv[4];
#pragma unroll
        for (int u = 0; u < 4; u++) wv[u] = *(const float4*)&Ws[(k + u) * 64 + cx];
#pragma unroll
        for (int r = 0; r < 4; r++) xv[r] = *(const float4*)&Xs[(ry + r) * 128 + k];
#pragma unroll
        for (int r = 0; r < 4; r++) {
            acc[r][0] += xv[r].x * wv[0].x + xv[r].y * wv[1].x + xv[r].z * wv[2].x + xv[r].w * wv[3].x;
            acc[r][1] += xv[r].x * wv[0].y + xv[r].y * wv[1].y + xv[r].z * wv[2].y + xv[r].w * wv[3].y;
            acc[r][2] += xv[r].x * wv[0].z + xv[r].y * wv[1].z + xv[r].z * wv[2].z + xv[r].w * wv[3].z;
            acc[r][3] += xv[r].x * wv[0].w + xv[r].y * wv[1].w + xv[r].z * wv[2].w + xv[r].w * wv[3].w;
        }
    }

    float b0 = b[cx], b1 = b[cx + 1], b2 = b[cx + 2], b3 = b[cx + 3];
#pragma unroll
    for (int r = 0; r < 4; r++) {
        int i = row0 + ry + r;
        float s = g_dv[i];
        float4 o;
        o.x = s * (acc[r][0] + b0);
        o.y = s * (acc[r][1] + b1);
        o.z = s * (acc[r][2] + b2);
        o.w = s * (acc[r][3] + b3);
        *(float4*)&g_Z[i * COUT + cx] = o;
    }
}

// ---------------- kernel 5: Y2[j] = de_j * sum_{i in j} Z[i]  (4-wide) ----------
__global__ void k_edge() {
    int w = (blockIdx.x * blockDim.x + threadIdx.x) >> 5;
    int lane = threadIdx.x & 31;
    if (w >= N_E) return;
    int t = g_off_e[w], end = g_off_e[w + 1];
    float a0 = 0.f, a1 = 0.f;
    for (; t + 4 <= end; t += 4) {
        int i0 = g_adj_e[t];
        int i1 = g_adj_e[t + 1];
        int i2 = g_adj_e[t + 2];
        int i3 = g_adj_e[t + 3];
        float z00 = g_Z[i0 * COUT + lane], z01 = g_Z[i0 * COUT + lane + 32];
        float z10 = g_Z[i1 * COUT + lane], z11 = g_Z[i1 * COUT + lane + 32];
        float z20 = g_Z[i2 * COUT + lane], z21 = g_Z[i2 * COUT + lane + 32];
        float z30 = g_Z[i3 * COUT + lane], z31 = g_Z[i3 * COUT + lane + 32];
        a0 += (z00 + z10) + (z20 + z30);
        a1 += (z01 + z11) + (z21 + z31);
    }
    for (; t < end; t++) {
        int i0 = g_adj_e[t];
        a0 += g_Z[i0 * COUT + lane];
        a1 += g_Z[i0 * COUT + lane + 32];
    }
    float de = g_de[w];
    g_Y2[w * COUT + lane]      = a0 * de;
    g_Y2[w * COUT + lane + 32] = a1 * de;
}

// ---------------- kernel 6: out = relu(dv .* (H @ Y2)) + counter reset ----------
__global__ void k_vertex(float* __restrict__ out) {
    int gt = blockIdx.x * blockDim.x + threadIdx.x;
    int w = gt >> 5;
    int lane = threadIdx.x & 31;
    if (w < N_V) {
        int t = g_off_v[w], end = g_off_v[w + 1];
        float a0 = 0.f, a1 = 0.f;
        for (; t + 4 <= end; t += 4) {
            int j0 = g_adj_v[t];
            int j1 = g_adj_v[t + 1];
            int j2 = g_adj_v[t + 2];
            int j3 = g_adj_v[t + 3];
            float y00 = g_Y2[j0 * COUT + lane], y01 = g_Y2[j0 * COUT + lane + 32];
            float y10 = g_Y2[j1 * COUT + lane], y11 = g_Y2[j1 * COUT + lane + 32];
            float y20 = g_Y2[j2 * COUT + lane], y21 = g_Y2[j2 * COUT + lane + 32];
            float y30 = g_Y2[j3 * COUT + lane], y31 = g_Y2[j3 * COUT + lane + 32];
            a0 += (y00 + y10) + (y20 + y30);
            a1 += (y01 + y11) + (y21 + y31);
        }
        for (; t < end; t++) {
            int j0 = g_adj_v[t];
            a0 += g_Y2[j0 * COUT + lane];
            a1 += g_Y2[j0 * COUT + lane + 32];
        }
        float dv = g_dv[w];
        float o0 = dv * a0;
        float o1 = dv * a1;
        out[w * COUT + lane]      = o0 > 0.f ? o0 : 0.f;
        out[w * COUT + lane + 32] = o1 > 0.f ? o1 : 0.f;
    }
    // tail: re-zero counters for the NEXT launch (stream-ordered; launch 0
    // covered by static zero-init of __device__ globals).
    if (gt < N_V) { g_deg_v[gt] = 0; g_cur_v[gt] = 0; }
    if (gt < N_E) { g_deg_e[gt] = 0; g_cur_e[gt] = 0; }
}

// ---------------- launch ----------------
extern "C" void kernel_launch(void* const* d_in, const int* in_sizes, int n_in,
                              void* d_out, int out_size) {
    const float* X = (const float*)d_in[0];   // (16384, 128)
    const float* H = (const float*)d_in[1];   // (16384, 8192)
    const float* W = (const float*)d_in[2];   // (64, 128)
    const float* b = (const float*)d_in[3];   // (64,)
    float* out = (float*)d_out;               // (16384, 64)

    k_extract    <<<EBLOCKS, ETHREADS>>>(H);
    k_scan_scales<<<2, 256>>>();
    k_bucket     <<<(EBLOCKS * CAPB) / 256, 256>>>();
    k_gemm       <<<N_V / 32, 128>>>(X, W, b);
    k_edge       <<<(N_E * 32) / 256, 256>>>();
    k_vertex     <<<(N_V * 32) / 256, 256>>>(out);
}

// round 8
// speedup vs baseline: 2.9162x; 1.0292x over previous
#include <cuda_runtime.h>
#include <stdint.h>

// Problem constants
#define N_V   16384
#define N_E   8192
#define CIN   128
#define COUT  64
#define LOG_M 13

// Extraction config (R1-proven, DO NOT TOUCH)
#define EBLOCKS  2048
#define ETHREADS 256
#define CAPB     512                       // COO slots per block (mean ~328, 10 sigma safe)
#define NTOT     (EBLOCKS*ETHREADS)        // 524288 threads
#define EITER    64                        // (N_V*N_E/4)/NTOT exactly

// Fused bucket+gemm launch
#define GEMMB2   256                       // GEMM blocks (64 rows each)
#define BUCKB    ((EBLOCKS*CAPB)/256)      // 4096 bucket blocks

// ---------------- scratch (device globals; no allocation) ----------------
__device__ int            g_deg_v[N_V];
__device__ int            g_deg_e[N_E];
__device__ int            g_cur_v[N_V];
__device__ int            g_cur_e[N_E];
__device__ int            g_off_v[N_V + 1];
__device__ int            g_off_e[N_E + 1];
__device__ int            g_blk_cnt[EBLOCKS];
__device__ unsigned int   g_coo[EBLOCKS * CAPB];     // packed (i<<13)|j
__device__ unsigned short g_adj_v[EBLOCKS * CAPB];   // CSR by vertex: edge ids
__device__ unsigned short g_adj_e[EBLOCKS * CAPB];   // CSC by edge: vertex ids
__device__ float          g_dv[N_V];
__device__ float          g_de[N_E];
__device__ float          g_Z[N_V * COUT];           // X W^T + b   (dv folded in k_edge)
__device__ float          g_Y2[N_E * COUT];          // de * (H^T @ dv.Z)

// ---------------- kernel 1: extract (EXACT R1 shape) ----------------
__global__ void k_extract(const float* __restrict__ H) {
    __shared__ int s_cnt;
    if (threadIdx.x == 0) s_cnt = 0;
    __syncthreads();

    const uint4* __restrict__ H4 = (const uint4*)H;
    int tid = blockIdx.x * ETHREADS + threadIdx.x;
    unsigned cooBase = blockIdx.x * CAPB;

#pragma unroll 4
    for (int it = 0; it < EITER; it++) {
        int v = tid + it * NTOT;
        uint4 h = H4[v];
        if ((h.x | h.y | h.z | h.w) == 0u) continue;   // ~98% of vectors
        int e = v * 4;
#pragma unroll
        for (int c = 0; c < 4; c++) {
            unsigned hv = (c == 0) ? h.x : (c == 1) ? h.y : (c == 2) ? h.z : h.w;
            if (hv) {
                int ee = e + c;
                int i = ee >> LOG_M;
                int j = ee & (N_E - 1);
                atomicAdd(&g_deg_v[i], 1);
                atomicAdd(&g_deg_e[j], 1);
                int p = atomicAdd(&s_cnt, 1);          // shared atomic: cheap
                if (p < CAPB)
                    g_coo[cooBase + p] = ((unsigned)i << LOG_M) | (unsigned)j;
            }
        }
    }
    __syncthreads();
    if (threadIdx.x == 0)
        g_blk_cnt[blockIdx.x] = (s_cnt < CAPB) ? s_cnt : CAPB;
}

// ---------------- kernel 2: prefix scan + scales fused (2 blocks x 256) --------
__device__ void scan_scale(int n, int per, const int* __restrict__ deg,
                           int* __restrict__ off, float* __restrict__ sc, bool isV) {
    __shared__ int part[256];
    int tid = threadIdx.x;
    int base = tid * per;
    int s = 0;
    for (int k = 0; k < per; k++) s += deg[base + k];
    part[tid] = s;
    __syncthreads();
    for (int d = 1; d < 256; d <<= 1) {
        int v = (tid >= d) ? part[tid - d] : 0;
        __syncthreads();
        part[tid] += v;
        __syncthreads();
    }
    int pre = tid ? part[tid - 1] : 0;
    for (int k = 0; k < per; k++) {
        int d = deg[base + k];
        off[base + k] = pre;
        pre += d;
        sc[base + k] = (d > 0) ? (isV ? rsqrtf((float)d) : 1.0f / (float)d) : 0.0f;
    }
    if (tid == 255) off[n] = pre;
}

__global__ void k_scan_scales() {
    if (blockIdx.x == 0) scan_scale(N_V, 64, g_deg_v, g_off_v, g_dv, true);
    else                 scan_scale(N_E, 32, g_deg_e, g_off_e, g_de, false);
}

// ---------------- kernel 3: GEMM (blocks 0..255) || bucket (blocks 256..) -------
// GEMM: Z[i][c] = sum_k X[i][k]*W[c][k] + b[c]   (NO dv here; folded into k_edge)
// 64-row X tile in smem (32KB, coalesced fill). Warp -> 8 rows, lane -> 2 cols.
// All Xs reads are warp-uniform (broadcast, conflict-free). W streamed via L1.
__global__ void __launch_bounds__(256)
k_gemm_bucket(const float* __restrict__ X,
              const float* __restrict__ W,
              const float* __restrict__ bias) {
    __shared__ float Xs[64 * 128];           // 32 KB
    const int tid = threadIdx.x;
    const int bx  = blockIdx.x;

    if (bx < GEMMB2) {
        int row0 = bx * 64;
        // coalesced X tile fill: 2048 float4 / 256 threads = 8 each
        const float4* __restrict__ Xg = (const float4*)(X + row0 * CIN);
        float4* Xs4 = (float4*)Xs;
#pragma unroll
        for (int t = 0; t < 8; t++) Xs4[tid + t * 256] = Xg[tid + t * 256];
        __syncthreads();

        const int wid  = tid >> 5;           // 0..7 -> rows wid*8..wid*8+7
        const int lane = tid & 31;           // cols (lane, lane+32)
        const int ry   = wid * 8;
        const float4* __restrict__ Wc0 = (const float4*)(W + lane * CIN);
        const float4* __restrict__ Wc1 = (const float4*)(W + (lane + 32) * CIN);

        float acc0[8] = {}, acc1[8] = {};
#pragma unroll
        for (int k4 = 0; k4 < 32; k4++) {
            float4 w0 = Wc0[k4];
            float4 w1 = Wc1[k4];
#pragma unroll
            for (int r = 0; r < 8; r++) {
                float4 xv = Xs4[(ry + r) * 32 + k4];   // warp-uniform -> broadcast
                acc0[r] += xv.x * w0.x + xv.y * w0.y + xv.z * w0.z + xv.w * w0.w;
                acc1[r] += xv.x * w1.x + xv.y * w1.y + xv.z * w1.z + xv.w * w1.w;
            }
        }
        float b0 = bias[lane], b1 = bias[lane + 32];
#pragma unroll
        for (int r = 0; r < 8; r++) {
            int i = row0 + ry + r;
            g_Z[i * COUT + lane]      = acc0[r] + b0;
            g_Z[i * COUT + lane + 32] = acc1[r] + b1;
        }
        return;
    }

    // ---- bucket path: COO -> CSR(vertex) + CSC(edge) ----
    int idx = (bx - GEMMB2) * 256 + tid;     // over EBLOCKS*CAPB slots
    int blk = idx >> 9;                      // CAPB = 512
    int loc = idx & (CAPB - 1);
    if (loc >= g_blk_cnt[blk]) return;
    unsigned p = g_coo[idx];
    int i = p >> LOG_M;
    int j = p & (N_E - 1);
    int pv = atomicAdd(&g_cur_v[i], 1);
    g_adj_v[g_off_v[i] + pv] = (unsigned short)j;
    int pe = atomicAdd(&g_cur_e[j], 1);
    g_adj_e[g_off_e[j] + pe] = (unsigned short)i;
}

// ---------------- kernel 4: Y2[j] = de_j * sum_{i in j} dv_i * Z[i] (4-wide) ----
__global__ void k_edge() {
    int w = (blockIdx.x * blockDim.x + threadIdx.x) >> 5;
    int lane = threadIdx.x & 31;
    if (w >= N_E) return;
    int t = g_off_e[w], end = g_off_e[w + 1];
    float a0 = 0.f, a1 = 0.f;
    for (; t + 4 <= end; t += 4) {
        int i0 = g_adj_e[t];
        int i1 = g_adj_e[t + 1];
        int i2 = g_adj_e[t + 2];
        int i3 = g_adj_e[t + 3];
        float s0 = g_dv[i0], s1 = g_dv[i1], s2 = g_dv[i2], s3 = g_dv[i3];
        float z00 = g_Z[i0 * COUT + lane], z01 = g_Z[i0 * COUT + lane + 32];
        float z10 = g_Z[i1 * COUT + lane], z11 = g_Z[i1 * COUT + lane + 32];
        float z20 = g_Z[i2 * COUT + lane], z21 = g_Z[i2 * COUT + lane + 32];
        float z30 = g_Z[i3 * COUT + lane], z31 = g_Z[i3 * COUT + lane + 32];
        a0 += (s0 * z00 + s1 * z10) + (s2 * z20 + s3 * z30);
        a1 += (s0 * z01 + s1 * z11) + (s2 * z21 + s3 * z31);
    }
    for (; t < end; t++) {
        int i0 = g_adj_e[t];
        float s0 = g_dv[i0];
        a0 += s0 * g_Z[i0 * COUT + lane];
        a1 += s0 * g_Z[i0 * COUT + lane + 32];
    }
    float de = g_de[w];
    g_Y2[w * COUT + lane]      = a0 * de;
    g_Y2[w * COUT + lane + 32] = a1 * de;
}

// ---------------- kernel 5: out = relu(dv .* (H @ Y2)) + counter reset ----------
__global__ void k_vertex(float* __restrict__ out) {
    int gt = blockIdx.x * blockDim.x + threadIdx.x;
    int w = gt >> 5;
    int lane = threadIdx.x & 31;
    if (w < N_V) {
        int t = g_off_v[w], end = g_off_v[w + 1];
        float a0 = 0.f, a1 = 0.f;
        for (; t + 4 <= end; t += 4) {
            int j0 = g_adj_v[t];
            int j1 = g_adj_v[t + 1];
            int j2 = g_adj_v[t + 2];
            int j3 = g_adj_v[t + 3];
            float y00 = g_Y2[j0 * COUT + lane], y01 = g_Y2[j0 * COUT + lane + 32];
            float y10 = g_Y2[j1 * COUT + lane], y11 = g_Y2[j1 * COUT + lane + 32];
            float y20 = g_Y2[j2 * COUT + lane], y21 = g_Y2[j2 * COUT + lane + 32];
            float y30 = g_Y2[j3 * COUT + lane], y31 = g_Y2[j3 * COUT + lane + 32];
            a0 += (y00 + y10) + (y20 + y30);
            a1 += (y01 + y11) + (y21 + y31);
        }
        for (; t < end; t++) {
            int j0 = g_adj_v[t];
            a0 += g_Y2[j0 * COUT + lane];
            a1 += g_Y2[j0 * COUT + lane + 32];
        }
        float dv = g_dv[w];
        float o0 = dv * a0;
        float o1 = dv * a1;
        out[w * COUT + lane]      = o0 > 0.f ? o0 : 0.f;
        out[w * COUT + lane + 32] = o1 > 0.f ? o1 : 0.f;
    }
    // tail: re-zero counters for the NEXT launch (stream-ordered; launch 0
    // covered by static zero-init of __device__ globals).
    if (gt < N_V) { g_deg_v[gt] = 0; g_cur_v[gt] = 0; }
    if (gt < N_E) { g_deg_e[gt] = 0; g_cur_e[gt] = 0; }
}

// ---------------- launch ----------------
extern "C" void kernel_launch(void* const* d_in, const int* in_sizes, int n_in,
                              void* d_out, int out_size) {
    const float* X = (const float*)d_in[0];   // (16384, 128)
    const float* H = (const float*)d_in[1];   // (16384, 8192)
    const float* W = (const float*)d_in[2];   // (64, 128)
    const float* b = (const float*)d_in[3];   // (64,)
    float* out = (float*)d_out;               // (16384, 64)

    k_extract    <<<EBLOCKS, ETHREADS>>>(H);
    k_scan_scales<<<2, 256>>>();
    k_gemm_bucket<<<GEMMB2 + BUCKB, 256>>>(X, W, b);
    k_edge       <<<(N_E * 32) / 256, 256>>>();
    k_vertex     <<<(N_V * 32) / 256, 256>>>(out);
}

// round 9
// speedup vs baseline: 3.3516x; 1.1493x over previous
#include <cuda_runtime.h>
#include <stdint.h>

// Problem constants
#define N_V   16384
#define N_E   8192
#define CIN   128
#define COUT  64
#define LOG_M 13

// Extraction config (R1-proven, DO NOT TOUCH)
#define EBLOCKS  2048
#define ETHREADS 256
#define CAPB     512                       // COO slots per block (mean ~328, 10 sigma safe)
#define NTOT     (EBLOCKS*ETHREADS)        // 524288 threads
#define EITER    64                        // (N_V*N_E/4)/NTOT exactly

// ---------------- scratch (device globals; no allocation) ----------------
__device__ int            g_deg_v[N_V];
__device__ int            g_deg_e[N_E];
__device__ int            g_cur_v[N_V];
__device__ int            g_cur_e[N_E];
__device__ int            g_off_v[N_V + 1];
__device__ int            g_off_e[N_E + 1];
__device__ int            g_blk_cnt[EBLOCKS];
__device__ unsigned int   g_coo[EBLOCKS * CAPB];     // packed (i<<13)|j
__device__ unsigned short g_adj_v[EBLOCKS * CAPB];   // CSR by vertex: edge ids
__device__ unsigned short g_adj_e[EBLOCKS * CAPB];   // CSC by edge: vertex ids
__device__ float          g_dv[N_V];
__device__ float          g_de[N_E];
__device__ float          g_Z[N_V * COUT];           // dv * (X W^T + b)
__device__ float          g_Y2[N_E * COUT];          // de * (H^T @ Z)

// ---------------- kernel 1: extract (EXACT R1 shape) ----------------
__global__ void k_extract(const float* __restrict__ H) {
    __shared__ int s_cnt;
    if (threadIdx.x == 0) s_cnt = 0;
    __syncthreads();

    const uint4* __restrict__ H4 = (const uint4*)H;
    int tid = blockIdx.x * ETHREADS + threadIdx.x;
    unsigned cooBase = blockIdx.x * CAPB;

#pragma unroll 4
    for (int it = 0; it < EITER; it++) {
        int v = tid + it * NTOT;
        uint4 h = H4[v];
        if ((h.x | h.y | h.z | h.w) == 0u) continue;   // ~98% of vectors
        int e = v * 4;
#pragma unroll
        for (int c = 0; c < 4; c++) {
            unsigned hv = (c == 0) ? h.x : (c == 1) ? h.y : (c == 2) ? h.z : h.w;
            if (hv) {
                int ee = e + c;
                int i = ee >> LOG_M;
                int j = ee & (N_E - 1);
                atomicAdd(&g_deg_v[i], 1);
                atomicAdd(&g_deg_e[j], 1);
                int p = atomicAdd(&s_cnt, 1);          // shared atomic: cheap
                if (p < CAPB)
                    g_coo[cooBase + p] = ((unsigned)i << LOG_M) | (unsigned)j;
            }
        }
    }
    __syncthreads();
    if (threadIdx.x == 0)
        g_blk_cnt[blockIdx.x] = (s_cnt < CAPB) ? s_cnt : CAPB;
}

// ---------------- kernel 2: scan + scales (R1's 1024-thread scan, scales folded) --
__device__ void scan_scale_1024(int n, const int* __restrict__ deg,
                                int* __restrict__ off, float* __restrict__ sc,
                                bool isV) {
    __shared__ int part[1024];
    int tid = threadIdx.x;
    int per = n >> 10;
    int base = tid * per;
    int s = 0;
    for (int k = 0; k < per; k++) s += deg[base + k];
    part[tid] = s;
    __syncthreads();
    for (int d = 1; d < 1024; d <<= 1) {
        int v = (tid >= d) ? part[tid - d] : 0;
        __syncthreads();
        part[tid] += v;
        __syncthreads();
    }
    int pre = tid ? part[tid - 1] : 0;
    for (int k = 0; k < per; k++) {
        int d = deg[base + k];
        off[base + k] = pre;
        pre += d;
        sc[base + k] = (d > 0) ? (isV ? rsqrtf((float)d) : 1.0f / (float)d) : 0.0f;
    }
    if (tid == 1023) off[n] = pre;
}

__global__ void k_scan_scales() {
    if (blockIdx.x == 0) scan_scale_1024(N_V, g_deg_v, g_off_v, g_dv, true);
    else                 scan_scale_1024(N_E, g_deg_e, g_off_e, g_de, false);
}

// ---------------- kernel 3: bucket (EXACT R1 shape) ----------------
__global__ void k_bucket() {
    int idx = blockIdx.x * blockDim.x + threadIdx.x;   // over EBLOCKS*CAPB slots
    int blk = idx >> 9;                                // CAPB = 512
    int loc = idx & (CAPB - 1);
    if (loc >= g_blk_cnt[blk]) return;
    unsigned p = g_coo[idx];
    int i = p >> LOG_M;
    int j = p & (N_E - 1);
    int pv = atomicAdd(&g_cur_v[i], 1);
    g_adj_v[g_off_v[i] + pv] = (unsigned short)j;
    int pe = atomicAdd(&g_cur_e[j], 1);
    g_adj_e[g_off_e[j] + pe] = (unsigned short)i;
}

// ---------------- kernel 4: GEMM  Z = dv .* (X W^T + b) ----------------
// R1 tile/shape; ONLY change: W read is coalesced (linear) and the smem store
// is XOR-swizzled (c' = c ^ (k & 28)) so fill has no scattered global loads.
// Swizzle keeps float4 alignment (both terms multiples of 4). Smem 48KB exact.
__global__ void k_gemm(const float* __restrict__ X,
                       const float* __restrict__ W,
                       const float* __restrict__ b) {
    __shared__ float Xs[32 * 128];   // 16 KB
    __shared__ float Ws[128 * 64];   // 32 KB  [k][c^swz]
    int tid = threadIdx.x;           // 128 threads
    int row0 = blockIdx.x * 32;

    const float4* __restrict__ Xg = (const float4*)(X + row0 * CIN);
    float4* Xs4 = (float4*)Xs;
#pragma unroll
    for (int t = 0; t < 8; t++) Xs4[tid + t * 128] = Xg[tid + t * 128];

    // Coalesced W fill: idx = c*128 + k  ->  read W[idx] linearly.
#pragma unroll
    for (int t = 0; t < 64; t++) {
        int idx = tid + t * 128;               // 0..8191
        int c = idx >> 7, k = idx & 127;
        Ws[k * 64 + (c ^ (k & 28))] = W[idx];
    }
    __syncthreads();

    int cx = (tid & 15) * 4;
    int ry = (tid >> 4) * 4;
    float acc[4][4] = {};

#pragma unroll
    for (int k = 0; k < 128; k += 4) {
        int swz = k & 28;                      // constant for u=0..3 (k%4==0)
        float4 wv[4], xv[4];
#pragma unroll
        for (int u = 0; u < 4; u++) wv[u] = *(const float4*)&Ws[(k + u) * 64 + (cx ^ swz)];
#pragma unroll
        for (int r = 0; r < 4; r++) xv[r] = *(const float4*)&Xs[(ry + r) * 128 + k];
#pragma unroll
        for (int r = 0; r < 4; r++) {
            acc[r][0] += xv[r].x * wv[0].x + xv[r].y * wv[1].x + xv[r].z * wv[2].x + xv[r].w * wv[3].x;
            acc[r][1] += xv[r].x * wv[0].y + xv[r].y * wv[1].y + xv[r].z * wv[2].y + xv[r].w * wv[3].y;
            acc[r][2] += xv[r].x * wv[0].z + xv[r].y * wv[1].z + xv[r].z * wv[2].z + xv[r].w * wv[3].z;
            acc[r][3] += xv[r].x * wv[0].w + xv[r].y * wv[1].w + xv[r].z * wv[2].w + xv[r].w * wv[3].w;
        }
    }

    float b0 = b[cx], b1 = b[cx + 1], b2 = b[cx + 2], b3 = b[cx + 3];
#pragma unroll
    for (int r = 0; r < 4; r++) {
        int i = row0 + ry + r;
        float s = g_dv[i];
        float4 o;
        o.x = s * (acc[r][0] + b0);
        o.y = s * (acc[r][1] + b1);
        o.z = s * (acc[r][2] + b2);
        o.w = s * (acc[r][3] + b3);
        *(float4*)&g_Z[i * COUT + cx] = o;
    }
}

// ---------------- kernel 5: Y2[j] = de_j * sum_{i in j} Z[i]  (4-wide) ----------
__global__ void k_edge() {
    int w = (blockIdx.x * blockDim.x + threadIdx.x) >> 5;
    int lane = threadIdx.x & 31;
    if (w >= N_E) return;
    int t = g_off_e[w], end = g_off_e[w + 1];
    float a0 = 0.f, a1 = 0.f;
    for (; t + 4 <= end; t += 4) {
        int i0 = g_adj_e[t];
        int i1 = g_adj_e[t + 1];
        int i2 = g_adj_e[t + 2];
        int i3 = g_adj_e[t + 3];
        float z00 = g_Z[i0 * COUT + lane], z01 = g_Z[i0 * COUT + lane + 32];
        float z10 = g_Z[i1 * COUT + lane], z11 = g_Z[i1 * COUT + lane + 32];
        float z20 = g_Z[i2 * COUT + lane], z21 = g_Z[i2 * COUT + lane + 32];
        float z30 = g_Z[i3 * COUT + lane], z31 = g_Z[i3 * COUT + lane + 32];
        a0 += (z00 + z10) + (z20 + z30);
        a1 += (z01 + z11) + (z21 + z31);
    }
    for (; t < end; t++) {
        int i0 = g_adj_e[t];
        a0 += g_Z[i0 * COUT + lane];
        a1 += g_Z[i0 * COUT + lane + 32];
    }
    float de = g_de[w];
    g_Y2[w * COUT + lane]      = a0 * de;
    g_Y2[w * COUT + lane + 32] = a1 * de;
}

// ---------------- kernel 6: out = relu(dv .* (H @ Y2)) + counter reset ----------
__global__ void k_vertex(float* __restrict__ out) {
    int gt = blockIdx.x * blockDim.x + threadIdx.x;
    int w = gt >> 5;
    int lane = threadIdx.x & 31;
    if (w < N_V) {
        int t = g_off_v[w], end = g_off_v[w + 1];
        float a0 = 0.f, a1 = 0.f;
        for (; t + 4 <= end; t += 4) {
            int j0 = g_adj_v[t];
            int j1 = g_adj_v[t + 1];
            int j2 = g_adj_v[t + 2];
            int j3 = g_adj_v[t + 3];
            float y00 = g_Y2[j0 * COUT + lane], y01 = g_Y2[j0 * COUT + lane + 32];
            float y10 = g_Y2[j1 * COUT + lane], y11 = g_Y2[j1 * COUT + lane + 32];
            float y20 = g_Y2[j2 * COUT + lane], y21 = g_Y2[j2 * COUT + lane + 32];
            float y30 = g_Y2[j3 * COUT + lane], y31 = g_Y2[j3 * COUT + lane + 32];
            a0 += (y00 + y10) + (y20 + y30);
            a1 += (y01 + y11) + (y21 + y31);
        }
        for (; t < end; t++) {
            int j0 = g_adj_v[t];
            a0 += g_Y2[j0 * COUT + lane];
            a1 += g_Y2[j0 * COUT + lane + 32];
        }
        float dv = g_dv[w];
        float o0 = dv * a0;
        float o1 = dv * a1;
        out[w * COUT + lane]      = o0 > 0.f ? o0 : 0.f;
        out[w * COUT + lane + 32] = o1 > 0.f ? o1 : 0.f;
    }
    // tail: re-zero counters for the NEXT launch (stream-ordered; launch 0
    // covered by static zero-init of __device__ globals).
    if (gt < N_V) { g_deg_v[gt] = 0; g_cur_v[gt] = 0; }
    if (gt < N_E) { g_deg_e[gt] = 0; g_cur_e[gt] = 0; }
}

// ---------------- launch ----------------
extern "C" void kernel_launch(void* const* d_in, const int* in_sizes, int n_in,
                              void* d_out, int out_size) {
    const float* X = (const float*)d_in[0];   // (16384, 128)
    const float* H = (const float*)d_in[1];   // (16384, 8192)
    const float* W = (const float*)d_in[2];   // (64, 128)
    const float* b = (const float*)d_in[3];   // (64,)
    float* out = (float*)d_out;               // (16384, 64)

    k_extract    <<<EBLOCKS, ETHREADS>>>(H);
    k_scan_scales<<<2, 1024>>>();
    k_bucket     <<<(EBLOCKS * CAPB) / 256, 256>>>();
    k_gemm       <<<N_V / 32, 128>>>(X, W, b);
    k_edge       <<<(N_E * 32) / 256, 256>>>();
    k_vertex     <<<(N_V * 32) / 256, 256>>>(out);
}